// round 16
// baseline (speedup 1.0000x reference)
#include <cuda_runtime.h>
#include <cuda_bf16.h>
#include <math.h>
#include <stdint.h>

#define B_ROWS 32768
#define D_IN   256
#define D_H    512
#define D_Q    1024
#define D_E    256
#define K_CAT  (D_IN + D_H)

typedef __nv_bfloat16 bf16;

static cudaStream_t g_s1;
static cudaEvent_t  g_evFork, g_evJoin;
static struct StreamInit {
    StreamInit(){
        cudaStreamCreateWithFlags(&g_s1, cudaStreamNonBlocking);
        cudaEventCreateWithFlags(&g_evFork, cudaEventDisableTiming);
        cudaEventCreateWithFlags(&g_evJoin, cudaEventDisableTiming);
    }
} g_streamInit;

// ---- scratch ----
__device__ float g_h1f[(size_t)B_ROWS*D_H];
__device__ float g_logits[(size_t)B_ROWS*D_Q];
__device__ bf16  g_xh[(size_t)B_ROWS*D_IN], g_xm[(size_t)B_ROWS*D_IN], g_xl[(size_t)B_ROWS*D_IN];
__device__ bf16  g_h1h[(size_t)B_ROWS*D_H], g_h1m[(size_t)B_ROWS*D_H], g_h1l[(size_t)B_ROWS*D_H];
__device__ bf16  g_hk1h[(size_t)B_ROWS*D_H], g_hk1m[(size_t)B_ROWS*D_H];
__device__ float g_hk2[(size_t)B_ROWS*D_H];
__device__ bf16  g_khotb[(size_t)B_ROWS*D_Q];
__device__ bf16  g_qh[(size_t)B_ROWS*D_E],  g_qm[(size_t)B_ROWS*D_E];
__device__ bf16  g_hdh[(size_t)B_ROWS*D_H], g_hdm[(size_t)B_ROWS*D_H];
__device__ float g_kclip[B_ROWS], g_invk[B_ROWS];
__device__ int   g_flag[B_ROWS];
__device__ float g_We2T[D_H*D_Q];
__device__ float g_Wfold[D_H*D_H];
__device__ float g_bfold[D_H];
__device__ bf16  g_Wch[D_H*K_CAT], g_Wcm[D_H*K_CAT];
__device__ bf16  g_Wk2h[D_H*D_H],  g_Wk2m[D_H*D_H];
__device__ bf16  g_Wcbh[D_E*D_Q],  g_Wcbm[D_E*D_Q];
__device__ bf16  g_Wd1h[D_H*D_E],  g_Wd1m[D_H*D_E];
__device__ bf16  g_Wd2h[D_IN*D_H], g_Wd2m[D_IN*D_H];

__global__ void split3_kernel(const float* __restrict__ s, bf16* __restrict__ h,
                              bf16* __restrict__ m, bf16* __restrict__ l, int n){
    for (int i = blockIdx.x*blockDim.x + threadIdx.x; i < n; i += gridDim.x*blockDim.x){
        float v = s[i];
        bf16 hb = __float2bfloat16(v);
        float r = v - __bfloat162float(hb);
        bf16 mb = __float2bfloat16(r);
        h[i] = hb; m[i] = mb;
        if (l) l[i] = __float2bfloat16(r - __bfloat162float(mb));
    }
}

__global__ void transpose_kernel(const float* __restrict__ We2, float* __restrict__ We2T){
    int i = blockIdx.x*blockDim.x + threadIdx.x;
    if (i >= D_H*D_Q) return;
    int n = i / D_Q, q = i % D_Q;
    We2T[i] = We2[(size_t)q*D_H + n];
}

__global__ void bfold_kernel(const float* __restrict__ Wk1, const float* __restrict__ bk1,
                             const float* __restrict__ be2, float* __restrict__ bfold){
    const int warp = blockIdx.x*(blockDim.x>>5) + (threadIdx.x>>5);
    const int lane = threadIdx.x & 31;
    if (warp >= D_H) return;
    const float* wr = Wk1 + (size_t)warp*(D_IN + D_Q) + D_IN;
    float s = 0.f;
    for (int q = lane; q < D_Q; q += 32) s += wr[q]*be2[q];
#pragma unroll
    for (int o = 16; o; o >>= 1) s += __shfl_xor_sync(0xffffffffu, s, o);
    if (lane == 0) bfold[warp] = bk1[warp] + s;
}

// assemble Wcat = [Wk1[:, :256] | Wfold], 2-way split
__global__ void assemble_split_kernel(const float* __restrict__ Wk1, const float* __restrict__ Wfold,
                                      bf16* __restrict__ h, bf16* __restrict__ m){
    for (int i = blockIdx.x*blockDim.x + threadIdx.x; i < D_H*K_CAT; i += gridDim.x*blockDim.x){
        int j = i / K_CAT, c = i % K_CAT;
        float v = (c < D_IN) ? Wk1[(size_t)j*(D_IN+D_Q) + c] : Wfold[(size_t)j*D_H + (c - D_IN)];
        bf16 hb = __float2bfloat16(v);
        h[i] = hb;
        m[i] = __float2bfloat16(v - __bfloat162float(hb));
    }
}

// exact fp32 k for flagged rows (serial fma through folded weights)
__global__ void kfix_kernel(const int* __restrict__ flag,
                            const float* __restrict__ x, const float* __restrict__ h1,
                            const float* __restrict__ Wk1, const float* __restrict__ Wfold,
                            const float* __restrict__ bfold,
                            const float* __restrict__ Wk2, const float* __restrict__ bk2,
                            const float* __restrict__ wk3, const float* __restrict__ bk3,
                            const float* __restrict__ kscale,
                            float* __restrict__ kclip, float* __restrict__ invk,
                            float* __restrict__ kout)
{
    const int row = blockIdx.x;
    if (!flag[row]) return;
    __shared__ float cat[K_CAT];
    __shared__ float hk1s[D_H];
    __shared__ float hk2s[D_H];
    const int tid = threadIdx.x;
    for (int j = tid; j < D_IN; j += 256)  cat[j] = x[(size_t)row*D_IN + j];
    for (int j = tid; j < D_H; j += 256)   cat[D_IN + j] = h1[(size_t)row*D_H + j];
    __syncthreads();
#pragma unroll
    for (int e = 0; e < 2; ++e){
        const int j = tid + e*256;
        float acc = 0.f;
        const float* wx = Wk1 + (size_t)j*(D_IN + D_Q);
        for (int c = 0; c < D_IN; ++c) acc = fmaf(cat[c], wx[c], acc);
        const float* wf = Wfold + (size_t)j*D_H;
        for (int c = 0; c < D_H; ++c) acc = fmaf(cat[D_IN + c], wf[c], acc);
        hk1s[j] = fmaxf(acc + bfold[j], 0.f);
    }
    __syncthreads();
#pragma unroll
    for (int e = 0; e < 2; ++e){
        const int j = tid + e*256;
        float acc = 0.f;
        const float* wr = Wk2 + (size_t)j*D_H;
        for (int c = 0; c < D_H; ++c) acc = fmaf(hk1s[c], wr[c], acc);
        hk2s[j] = fmaxf(acc + bk2[j], 0.f);
    }
    __syncthreads();
    if (tid < 32){
        float s = 0.f;
        for (int c = tid; c < D_H; c += 32) s += hk2s[c]*wk3[c];
#pragma unroll
        for (int o = 16; o; o >>= 1) s += __shfl_xor_sync(0xffffffffu, s, o);
        if (tid == 0){
            float z = s + bk3[0];
            float k = (1.f/(1.f + expf(-z))) * 1024.f;
            float ks = 1.f/(1.f + expf(-kscale[0]));
            k = fminf(fmaxf(k*ks*2.f, 1.f), 1024.f);
            kclip[row] = k; invk[row] = 1.f/k;
            if (kout) kout[row] = k;
        }
    }
}

// ---- packed dual-fp32 FMA ----
static __device__ __forceinline__ uint64_t f32x2_pack(float lo, float hi){
    uint64_t r; asm("mov.b64 %0, {%1,%2};" : "=l"(r) : "f"(lo), "f"(hi)); return r;
}
static __device__ __forceinline__ void f32x2_unpack(uint64_t v, float& lo, float& hi){
    asm("mov.b64 {%0,%1}, %2;" : "=f"(lo), "=f"(hi) : "l"(v));
}
static __device__ __forceinline__ void f32x2_fma(uint64_t& c, uint64_t a, uint64_t b){
    asm("fma.rn.f32x2 %0, %1, %2, %0;" : "+l"(c) : "l"(a), "l"(b));
}

// ===================== fp32 SGEMM (exact path) =====================
#define BM 128
#define BN 128
#define BK 16
#define TM 8
#define TN 8

template<int OSPL>
__global__ void __launch_bounds__(256, 2)
sgemm_kernel(int N, int K,
             const float* __restrict__ A0, int lda0, int K0,
             const float* __restrict__ A1, int lda1,
             const float* __restrict__ W,
             const float* __restrict__ bias,
             float* __restrict__ C, int ldc, int do_relu,
             bf16* __restrict__ Ch, bf16* __restrict__ Cm, bf16* __restrict__ Cl)
{
    __shared__ float As[2][BK][BM];
    __shared__ float Bs[2][BK][BN];

    const int tid  = threadIdx.x;
    const int bm   = blockIdx.y * BM;
    const int bn   = blockIdx.x * BN;
    const int tm   = (tid >> 4) * TM;
    const int tn   = (tid & 15) * TN;
    const int lrow = tid >> 2;
    const int lcol = (tid & 3) << 2;

    uint64_t acc2[TM][TN/2];
#pragma unroll
    for (int i = 0; i < TM; ++i)
#pragma unroll
        for (int jp = 0; jp < TN/2; ++jp) acc2[i][jp] = 0ull;

    const int nT = K / BK;
    float4 a0, a1, b0, b1;

#define FETCH(t) do {                                                         \
    int k0_ = (t) * BK;                                                       \
    const float* Ap_; int la_; int kk_;                                       \
    if (k0_ < K0) { Ap_ = A0; la_ = lda0; kk_ = k0_; }                        \
    else          { Ap_ = A1; la_ = lda1; kk_ = k0_ - K0; }                   \
    a0 = *(const float4*)(Ap_ + (size_t)(bm + lrow)      * la_ + kk_ + lcol); \
    a1 = *(const float4*)(Ap_ + (size_t)(bm + lrow + 64) * la_ + kk_ + lcol); \
    b0 = *(const float4*)(W   + (size_t)(bn + lrow)      * K   + k0_ + lcol); \
    b1 = *(const float4*)(W   + (size_t)(bn + lrow + 64) * K   + k0_ + lcol); \
} while (0)

#define STASH(bf) do {                                              \
    As[bf][lcol+0][lrow]    = a0.x; As[bf][lcol+1][lrow]    = a0.y; \
    As[bf][lcol+2][lrow]    = a0.z; As[bf][lcol+3][lrow]    = a0.w; \
    As[bf][lcol+0][lrow+64] = a1.x; As[bf][lcol+1][lrow+64] = a1.y; \
    As[bf][lcol+2][lrow+64] = a1.z; As[bf][lcol+3][lrow+64] = a1.w; \
    Bs[bf][lcol+0][lrow]    = b0.x; Bs[bf][lcol+1][lrow]    = b0.y; \
    Bs[bf][lcol+2][lrow]    = b0.z; Bs[bf][lcol+3][lrow]    = b0.w; \
    Bs[bf][lcol+0][lrow+64] = b1.x; Bs[bf][lcol+1][lrow+64] = b1.y; \
    Bs[bf][lcol+2][lrow+64] = b1.z; Bs[bf][lcol+3][lrow+64] = b1.w; \
} while (0)

    FETCH(0);
    STASH(0);
    __syncthreads();

    int buf = 0;
    for (int t = 0; t < nT; ++t) {
        if (t + 1 < nT) FETCH(t + 1);
#pragma unroll
        for (int kk = 0; kk < BK; ++kk) {
            float a[TM];
            float4 bv0, bv1;
            *(float4*)&a[0] = *(const float4*)&As[buf][kk][tm];
            *(float4*)&a[4] = *(const float4*)&As[buf][kk][tm + 4];
            bv0 = *(const float4*)&Bs[buf][kk][tn];
            bv1 = *(const float4*)&Bs[buf][kk][tn + 4];
            uint64_t bp[TN/2];
            bp[0] = f32x2_pack(bv0.x, bv0.y);
            bp[1] = f32x2_pack(bv0.z, bv0.w);
            bp[2] = f32x2_pack(bv1.x, bv1.y);
            bp[3] = f32x2_pack(bv1.z, bv1.w);
#pragma unroll
            for (int i = 0; i < TM; ++i) {
                uint64_t ad = f32x2_pack(a[i], a[i]);
#pragma unroll
                for (int jp = 0; jp < TN/2; ++jp)
                    f32x2_fma(acc2[i][jp], ad, bp[jp]);
            }
        }
        if (t + 1 < nT) STASH(buf ^ 1);
        __syncthreads();
        buf ^= 1;
    }

    float bj[TN];
#pragma unroll
    for (int j = 0; j < TN; ++j) bj[j] = bias ? bias[bn + tn + j] : 0.f;

#pragma unroll
    for (int i = 0; i < TM; ++i) {
        const int row = bm + tm + i;
        float v[TN];
#pragma unroll
        for (int jp = 0; jp < TN/2; ++jp)
            f32x2_unpack(acc2[i][jp], v[2*jp], v[2*jp+1]);
#pragma unroll
        for (int j = 0; j < TN; ++j) {
            float t = v[j] + bj[j];
            if (do_relu) t = fmaxf(t, 0.f);
            v[j] = t;
        }
        float* cp = C + (size_t)row * ldc + bn + tn;
        *(float4*)cp       = make_float4(v[0], v[1], v[2], v[3]);
        *(float4*)(cp + 4) = make_float4(v[4], v[5], v[6], v[7]);
        if (OSPL == 3){
            uint32_t ph[4], pm[4], pl[4];
#pragma unroll
            for (int jp = 0; jp < 4; ++jp){
                float v0 = v[2*jp], v1 = v[2*jp+1];
                bf16 h0 = __float2bfloat16(v0), h1 = __float2bfloat16(v1);
                float r0 = v0 - __bfloat162float(h0), r1 = v1 - __bfloat162float(h1);
                bf16 m0 = __float2bfloat16(r0), m1 = __float2bfloat16(r1);
                bf16 l0 = __float2bfloat16(r0 - __bfloat162float(m0));
                bf16 l1 = __float2bfloat16(r1 - __bfloat162float(m1));
                ph[jp] = ((uint32_t)__bfloat16_as_ushort(h1) << 16) | __bfloat16_as_ushort(h0);
                pm[jp] = ((uint32_t)__bfloat16_as_ushort(m1) << 16) | __bfloat16_as_ushort(m0);
                pl[jp] = ((uint32_t)__bfloat16_as_ushort(l1) << 16) | __bfloat16_as_ushort(l0);
            }
            *(uint4*)(Ch + (size_t)row*ldc + bn + tn) = make_uint4(ph[0], ph[1], ph[2], ph[3]);
            *(uint4*)(Cm + (size_t)row*ldc + bn + tn) = make_uint4(pm[0], pm[1], pm[2], pm[3]);
            *(uint4*)(Cl + (size_t)row*ldc + bn + tn) = make_uint4(pl[0], pl[1], pl[2], pl[3]);
        }
    }
#undef FETCH
#undef STASH
}

// =============== HMMA multi-term split-bf16 GEMM ===============
#define LDSM 40
#define TILE_E (128*LDSM)

static __device__ __forceinline__ void cpa16(bf16* dst, const bf16* src){
    uint32_t d = (uint32_t)__cvta_generic_to_shared(dst);
    asm volatile("cp.async.cg.shared.global [%0], [%1], 16;" :: "r"(d), "l"(src));
}
static __device__ __forceinline__ void mma16816(float* c, const uint32_t* a, const uint32_t* b){
    asm volatile("mma.sync.aligned.m16n8k16.row.col.f32.bf16.bf16.f32 "
        "{%0,%1,%2,%3},{%4,%5,%6,%7},{%8,%9},{%0,%1,%2,%3};"
        : "+f"(c[0]), "+f"(c[1]), "+f"(c[2]), "+f"(c[3])
        : "r"(a[0]), "r"(a[1]), "r"(a[2]), "r"(a[3]), "r"(b[0]), "r"(b[1]));
}

template<int NA, int NB, int MS, bool RELU, bool OF32, int OSPL>
__global__ void __launch_bounds__(256,1)
gemm_mma(int K, int K0, int lda0, int lda1,
         const bf16* __restrict__ A0h, const bf16* __restrict__ A0m,
         const bf16* __restrict__ A1h, const bf16* __restrict__ A1m,
         const bf16* __restrict__ B0,  const bf16* __restrict__ B1,
         const float* __restrict__ bias, const float* __restrict__ rowScale,
         float* __restrict__ C32, bf16* __restrict__ Ch, bf16* __restrict__ Cm, int ldc)
{
    extern __shared__ bf16 sm[];
    constexpr int NARR = NA + NB;
    const int tid = threadIdx.x, lane = tid & 31, wid = tid >> 5;
    const int bm = blockIdx.y*128, bn = blockIdx.x*128;
    const int wm = (wid >> 2)*64, wn = (wid & 3)*32;

    float acc[4][4][4];
#pragma unroll
    for (int mi = 0; mi < 4; ++mi)
#pragma unroll
        for (int ni = 0; ni < 4; ++ni)
#pragma unroll
            for (int e = 0; e < 4; ++e) acc[mi][ni][e] = 0.f;

    const int nT = K / 32;

    auto loadStage = [&](int t, int stage){
        bf16* base = sm + (size_t)stage*NARR*TILE_E;
        const int kc = t*32;
        const bf16* Aarr[2]; int ld, co;
        if (kc < K0){ Aarr[0]=A0h; Aarr[1]=A0m; ld=lda0; co=kc; }
        else        { Aarr[0]=A1h; Aarr[1]=A1m; ld=lda1; co=kc-K0; }
        const bf16* Barr[2] = {B0, B1};
#pragma unroll
        for (int arr = 0; arr < NA; ++arr)
#pragma unroll
            for (int s = tid; s < 512; s += 256){
                int r = s >> 2, c = s & 3;
                cpa16(base + arr*TILE_E + r*LDSM + c*8, Aarr[arr] + (size_t)(bm + r)*ld + co + c*8);
            }
#pragma unroll
        for (int arr = 0; arr < NB; ++arr)
#pragma unroll
            for (int s = tid; s < 512; s += 256){
                int r = s >> 2, c = s & 3;
                cpa16(base + (NA+arr)*TILE_E + r*LDSM + c*8, Barr[arr] + (size_t)(bn + r)*K + kc + c*8);
            }
        asm volatile("cp.async.commit_group;" ::: "memory");
    };

    loadStage(0, 0);

    for (int t = 0; t < nT; ++t){
        const int stage = t & 1;
        if (t + 1 < nT){
            loadStage(t + 1, stage ^ 1);
            asm volatile("cp.async.wait_group 1;" ::: "memory");
        } else {
            asm volatile("cp.async.wait_group 0;" ::: "memory");
        }
        __syncthreads();

        const bf16* base = sm + (size_t)stage*NARR*TILE_E;
#pragma unroll
        for (int ks = 0; ks < 2; ++ks){
            const int k0 = ks*16 + (lane & 3)*2;
            const int ar = wm + (lane >> 2);
            uint32_t afr[NA][4][4], bfr[NB][4][2];
#pragma unroll
            for (int arr = 0; arr < NA; ++arr){
                const bf16* sA = base + arr*TILE_E;
#pragma unroll
                for (int mi = 0; mi < 4; ++mi){
                    const bf16* p = sA + (size_t)(ar + mi*16)*LDSM + k0;
                    afr[arr][mi][0] = *(const uint32_t*)(p);
                    afr[arr][mi][1] = *(const uint32_t*)(p + 8*LDSM);
                    afr[arr][mi][2] = *(const uint32_t*)(p + 8);
                    afr[arr][mi][3] = *(const uint32_t*)(p + 8*LDSM + 8);
                }
            }
#pragma unroll
            for (int arr = 0; arr < NB; ++arr){
                const bf16* sB = base + (NA+arr)*TILE_E;
#pragma unroll
                for (int ni = 0; ni < 4; ++ni){
                    const bf16* p = sB + (size_t)(wn + ni*8 + (lane >> 2))*LDSM + k0;
                    bfr[arr][ni][0] = *(const uint32_t*)(p);
                    bfr[arr][ni][1] = *(const uint32_t*)(p + 8);
                }
            }
#pragma unroll
            for (int a = 0; a < NA; ++a)
#pragma unroll
                for (int b = 0; b < NB; ++b){
                    if (a + b <= MS){
#pragma unroll
                        for (int mi = 0; mi < 4; ++mi)
#pragma unroll
                            for (int ni = 0; ni < 4; ++ni)
                                mma16816(acc[mi][ni], afr[a][mi], bfr[b][ni]);
                    }
                }
        }
        __syncthreads();
    }

#pragma unroll
    for (int mi = 0; mi < 4; ++mi){
        const int r0 = bm + wm + mi*16 + (lane >> 2);
        const int r1 = r0 + 8;
        const float rs0 = rowScale ? rowScale[r0] : 1.f;
        const float rs1 = rowScale ? rowScale[r1] : 1.f;
#pragma unroll
        for (int ni = 0; ni < 4; ++ni){
            const int c0 = bn + wn + ni*8 + (lane & 3)*2;
            const float b0 = bias ? bias[c0] : 0.f;
            const float b1 = bias ? bias[c0 + 1] : 0.f;
            float v00 = acc[mi][ni][0] + b0, v01 = acc[mi][ni][1] + b1;
            float v10 = acc[mi][ni][2] + b0, v11 = acc[mi][ni][3] + b1;
            if (RELU){ v00 = fmaxf(v00, 0.f); v01 = fmaxf(v01, 0.f);
                       v10 = fmaxf(v10, 0.f); v11 = fmaxf(v11, 0.f); }
            v00 *= rs0; v01 *= rs0; v10 *= rs1; v11 *= rs1;
            if (OF32){
                *(float2*)(C32 + (size_t)r0*ldc + c0) = make_float2(v00, v01);
                *(float2*)(C32 + (size_t)r1*ldc + c0) = make_float2(v10, v11);
            }
            if (OSPL >= 2){
                bf16 h00 = __float2bfloat16(v00), h01 = __float2bfloat16(v01);
                bf16 h10 = __float2bfloat16(v10), h11 = __float2bfloat16(v11);
                bf16 m00 = __float2bfloat16(v00 - __bfloat162float(h00));
                bf16 m01 = __float2bfloat16(v01 - __bfloat162float(h01));
                bf16 m10 = __float2bfloat16(v10 - __bfloat162float(h10));
                bf16 m11 = __float2bfloat16(v11 - __bfloat162float(h11));
                *(uint32_t*)(Ch + (size_t)r0*ldc + c0) =
                    ((uint32_t)__bfloat16_as_ushort(h01) << 16) | __bfloat16_as_ushort(h00);
                *(uint32_t*)(Ch + (size_t)r1*ldc + c0) =
                    ((uint32_t)__bfloat16_as_ushort(h11) << 16) | __bfloat16_as_ushort(h10);
                *(uint32_t*)(Cm + (size_t)r0*ldc + c0) =
                    ((uint32_t)__bfloat16_as_ushort(m01) << 16) | __bfloat16_as_ushort(m00);
                *(uint32_t*)(Cm + (size_t)r1*ldc + c0) =
                    ((uint32_t)__bfloat16_as_ushort(m11) << 16) | __bfloat16_as_ushort(m10);
            }
        }
    }
}

// kpred with ceil-boundary guard flag
#define KGUARD 4e-3f
__global__ void kpred_kernel(const float* __restrict__ hk2, const float* __restrict__ wk3,
                             const float* __restrict__ bk3, const float* __restrict__ kscale,
                             float* __restrict__ kclip, float* __restrict__ invk,
                             float* __restrict__ kout, int* __restrict__ flag)
{
    __shared__ float ws[D_H];
    for (int j = threadIdx.x; j < D_H; j += blockDim.x) ws[j] = wk3[j];
    __syncthreads();
    const int warp = blockIdx.x*(blockDim.x>>5) + (threadIdx.x>>5);
    const int lane = threadIdx.x & 31;
    if (warp >= B_ROWS) return;
    const float* h = hk2 + (size_t)warp*D_H;
    float s = 0.f;
    for (int j = lane; j < D_H; j += 32) s += h[j]*ws[j];
#pragma unroll
    for (int o = 16; o; o >>= 1) s += __shfl_xor_sync(0xffffffffu, s, o);
    if (lane == 0){
        float z = s + bk3[0];
        float k = (1.f/(1.f + expf(-z))) * 1024.f;
        float ks = 1.f/(1.f + expf(-kscale[0]));
        k = fminf(fmaxf(k*ks*2.f, 1.f), 1024.f);
        kclip[warp] = k; invk[warp] = 1.f/k;
        if (kout) kout[warp] = k;
        float fr = k - floorf(k);
        flag[warp] = (fr < KGUARD || fr > 1.f - KGUARD || k < 1.f + KGUARD) ? 1 : 0;
    }
}

__global__ void topk_kernel(const float* __restrict__ logits, const float* __restrict__ kclip,
                            float* __restrict__ khot, bf16* __restrict__ khotb)
{
    __shared__ unsigned keys[D_Q];
    __shared__ int hist[256], scanbuf[256], warpsum[8], sBin;
    const int row = blockIdx.x, tid = threadIdx.x;
    float4 v = ((const float4*)(logits + (size_t)row*D_Q))[tid];
    { unsigned u;
      u=__float_as_uint(v.x); keys[tid*4+0]=(int)u>=0?(u|0x80000000u):~u;
      u=__float_as_uint(v.y); keys[tid*4+1]=(int)u>=0?(u|0x80000000u):~u;
      u=__float_as_uint(v.z); keys[tid*4+2]=(int)u>=0?(u|0x80000000u):~u;
      u=__float_as_uint(v.w); keys[tid*4+3]=(int)u>=0?(u|0x80000000u):~u; }
    int c = (int)ceilf(kclip[row]); c = max(1, min(D_Q, c));
    __syncthreads();
    unsigned prefix = 0; int want = c;
#pragma unroll
    for (int byte = 3; byte >= 0; --byte){
        hist[tid] = 0; __syncthreads();
        const unsigned mask = (byte==3) ? 0u : (0xFFFFFFFFu << ((byte+1)*8));
#pragma unroll
        for (int e = 0; e < 4; ++e){
            unsigned kk = keys[tid*4+e];
            if ((kk & mask) == prefix) atomicAdd(&hist[(kk >> (byte*8)) & 0xFF], 1);
        }
        __syncthreads();
        scanbuf[tid] = hist[tid]; __syncthreads();
        for (int d = 1; d < 256; d <<= 1){
            int add = (tid+d < 256) ? scanbuf[tid+d] : 0; __syncthreads();
            scanbuf[tid] += add; __syncthreads();
        }
        int nb = (tid < 255) ? scanbuf[tid+1] : 0;
        if (scanbuf[tid] >= want && nb < want) sBin = tid;
        __syncthreads();
        int bin = sBin;
        want -= (bin < 255) ? scanbuf[bin+1] : 0;
        prefix |= ((unsigned)bin) << (byte*8);
        __syncthreads();
    }
    const unsigned thr = prefix; const int rem = want;
    int gtf[4], eqf[4], pre[4], lc = 0;
#pragma unroll
    for (int e = 0; e < 4; ++e){
        unsigned kk = keys[tid*4+e];
        gtf[e] = (kk > thr); eqf[e] = (kk == thr); pre[e] = lc; lc += eqf[e];
    }
    const int lane = tid & 31, wid = tid >> 5;
    int inc = lc;
#pragma unroll
    for (int o = 1; o < 32; o <<= 1){ int y = __shfl_up_sync(0xffffffffu, inc, o); if (lane >= o) inc += y; }
    if (lane == 31) warpsum[wid] = inc;
    __syncthreads();
    if (tid == 0){ int run = 0; for (int i = 0; i < 8; ++i){ int t = warpsum[i]; warpsum[i] = run; run += t; } }
    __syncthreads();
    const int base = warpsum[wid] + inc - lc;
    float4 o;
    o.x = (gtf[0] || (eqf[0] && (base+pre[0]) < rem)) ? 1.f : 0.f;
    o.y = (gtf[1] || (eqf[1] && (base+pre[1]) < rem)) ? 1.f : 0.f;
    o.z = (gtf[2] || (eqf[2] && (base+pre[2]) < rem)) ? 1.f : 0.f;
    o.w = (gtf[3] || (eqf[3] && (base+pre[3]) < rem)) ? 1.f : 0.f;
    ((float4*)(khot + (size_t)row*D_Q))[tid] = o;
    uint32_t p0 = ((uint32_t)__bfloat16_as_ushort(__float2bfloat16(o.y)) << 16) | __bfloat16_as_ushort(__float2bfloat16(o.x));
    uint32_t p1 = ((uint32_t)__bfloat16_as_ushort(__float2bfloat16(o.w)) << 16) | __bfloat16_as_ushort(__float2bfloat16(o.z));
    ((uint2*)(khotb + (size_t)row*D_Q))[tid] = make_uint2(p0, p1);
}

__global__ void tail_kernel(float* zptr){ *zptr = 0.f; }

extern "C" void kernel_launch(void* const* d_in, const int* in_sizes, int n_in,
                              void* d_out, int out_size)
{
    const float* x      = (const float*)d_in[0];
    const float* We1    = (const float*)d_in[1];
    const float* be1    = (const float*)d_in[2];
    const float* We2    = (const float*)d_in[3];
    const float* be2    = (const float*)d_in[4];
    const float* Wcb    = (const float*)d_in[5];
    const float* Wd1    = (const float*)d_in[6];
    const float* bd1    = (const float*)d_in[7];
    const float* Wd2    = (const float*)d_in[8];
    const float* bd2    = (const float*)d_in[9];
    const float* Wk1    = (const float*)d_in[10];
    const float* bk1    = (const float*)d_in[11];
    const float* Wk2    = (const float*)d_in[12];
    const float* bk2    = (const float*)d_in[13];
    const float* Wk3    = (const float*)d_in[14];
    const float* bk3    = (const float*)d_in[15];
    const float* kscale = (const float*)d_in[16];

    bf16 *xh,*xm,*xl,*h1h,*h1m,*h1l,*hk1h,*hk1m,*khotb,*qh,*qm,*hdh,*hdm;
    bf16 *Wch,*Wcm,*Wk2h,*Wk2m,*Wcbh,*Wcbm,*Wd1h,*Wd1m,*Wd2h,*Wd2m;
    float *h1f,*logits,*hk2,*kclip,*invk,*We2T,*Wfold,*bfold;
    int *flag;
    cudaGetSymbolAddress((void**)&h1f,g_h1f);
    cudaGetSymbolAddress((void**)&logits,g_logits);
    cudaGetSymbolAddress((void**)&xh,g_xh);     cudaGetSymbolAddress((void**)&xm,g_xm);
    cudaGetSymbolAddress((void**)&xl,g_xl);
    cudaGetSymbolAddress((void**)&h1h,g_h1h);   cudaGetSymbolAddress((void**)&h1m,g_h1m);
    cudaGetSymbolAddress((void**)&h1l,g_h1l);
    cudaGetSymbolAddress((void**)&hk1h,g_hk1h); cudaGetSymbolAddress((void**)&hk1m,g_hk1m);
    cudaGetSymbolAddress((void**)&hk2,g_hk2);
    cudaGetSymbolAddress((void**)&khotb,g_khotb);
    cudaGetSymbolAddress((void**)&qh,g_qh);     cudaGetSymbolAddress((void**)&qm,g_qm);
    cudaGetSymbolAddress((void**)&hdh,g_hdh);   cudaGetSymbolAddress((void**)&hdm,g_hdm);
    cudaGetSymbolAddress((void**)&We2T,g_We2T); cudaGetSymbolAddress((void**)&Wfold,g_Wfold);
    cudaGetSymbolAddress((void**)&bfold,g_bfold);
    cudaGetSymbolAddress((void**)&Wch,g_Wch);   cudaGetSymbolAddress((void**)&Wcm,g_Wcm);
    cudaGetSymbolAddress((void**)&Wk2h,g_Wk2h); cudaGetSymbolAddress((void**)&Wk2m,g_Wk2m);
    cudaGetSymbolAddress((void**)&Wcbh,g_Wcbh); cudaGetSymbolAddress((void**)&Wcbm,g_Wcbm);
    cudaGetSymbolAddress((void**)&Wd1h,g_Wd1h); cudaGetSymbolAddress((void**)&Wd1m,g_Wd1m);
    cudaGetSymbolAddress((void**)&Wd2h,g_Wd2h); cudaGetSymbolAddress((void**)&Wd2m,g_Wd2m);
    cudaGetSymbolAddress((void**)&kclip,g_kclip); cudaGetSymbolAddress((void**)&invk,g_invk);
    cudaGetSymbolAddress((void**)&flag,g_flag);

    float* out = (float*)d_out;
    const long long reconN = (long long)B_ROWS*D_IN, khotN = (long long)B_ROWS*D_Q;
    const long long osz = (long long)out_size;
    float* khot = logits;
    if (osz >= reconN + khotN) khot = out + reconN;
    float *kout = nullptr, *zptr = nullptr;
    const long long tail = osz - (reconN + khotN);
    if (tail == 1 + (long long)B_ROWS){ zptr = out + reconN + khotN; kout = zptr + 1; }
    else if (tail == (long long)B_ROWS){ kout = out + reconN + khotN; }

    const int SMEM4 = 2*4*TILE_E*(int)sizeof(bf16);
    const int SMEM3 = 2*3*TILE_E*(int)sizeof(bf16);
    cudaFuncSetAttribute(gemm_mma<2,2,1,true ,false,2>, cudaFuncAttributeMaxDynamicSharedMemorySize, SMEM4);
    cudaFuncSetAttribute(gemm_mma<2,2,1,true ,true ,0>, cudaFuncAttributeMaxDynamicSharedMemorySize, SMEM4);
    cudaFuncSetAttribute(gemm_mma<1,2,1,false,false,2>, cudaFuncAttributeMaxDynamicSharedMemorySize, SMEM3);
    cudaFuncSetAttribute(gemm_mma<2,2,1,false,true ,0>, cudaFuncAttributeMaxDynamicSharedMemorySize, SMEM4);

    // ---- fold precompute ----
    transpose_kernel<<<(D_H*D_Q + 255)/256, 256>>>(We2, We2T);
    sgemm_kernel<0><<<dim3(D_H/BN, D_H/BM), 256>>>(D_H, D_Q, Wk1 + D_IN, D_IN + D_Q, D_Q,
        nullptr, 0, We2T, nullptr, Wfold, D_H, 0, nullptr, nullptr, nullptr);
    bfold_kernel<<<(D_H*32 + 255)/256, 256>>>(Wk1, bk1, be2, bfold);
    assemble_split_kernel<<<256, 256>>>(Wk1, Wfold, Wch, Wcm);

    // ---- splits ----
    split3_kernel<<<1024,256>>>(x,   xh,   xm,   xl,     B_ROWS*D_IN);
    split3_kernel<<<128 ,256>>>(Wk2, Wk2h, Wk2m, nullptr, D_H*D_H);
    split3_kernel<<<128 ,256>>>(Wcb, Wcbh, Wcbm, nullptr, D_E*D_Q);
    split3_kernel<<<128 ,256>>>(Wd1, Wd1h, Wd1m, nullptr, D_H*D_E);
    split3_kernel<<<128 ,256>>>(Wd2, Wd2h, Wd2m, nullptr, D_IN*D_H);

    const dim3 blk(256);
    const int GY = B_ROWS/128;

    // ---- e1 (fp32 exact; emits h1 fp32 + fused 3-way split) ----
    sgemm_kernel<3><<<dim3(D_H/BN, GY), blk>>>(D_H, D_IN, x, D_IN, D_IN,
        nullptr, 0, We1, be1, h1f, D_H, 1, h1h, h1m, h1l);

    // ---- FORK: 3-term k-path (tensor) || e2 fp32 (fma pipe) ----
    cudaEventRecord(g_evFork, 0);
    cudaStreamWaitEvent(g_s1, g_evFork, 0);

    gemm_mma<2,2,1,true ,false,2><<<dim3(D_H/128,GY),256,SMEM4,g_s1>>>(K_CAT, D_IN, D_IN, D_H,
        xh, xm, h1h, h1m, Wch, Wcm, bfold, nullptr, nullptr, hk1h, hk1m, D_H);
    gemm_mma<2,2,1,true ,true ,0><<<dim3(D_H/128,GY),256,SMEM4,g_s1>>>(D_H, D_H, D_H, 0,
        hk1h, hk1m, nullptr, nullptr, Wk2h, Wk2m, bk2, nullptr, hk2, nullptr, nullptr, D_H);
    kpred_kernel<<<B_ROWS/8,256,0,g_s1>>>(hk2, Wk3, bk3, kscale, kclip, invk, kout, flag);
    kfix_kernel<<<B_ROWS,256,0,g_s1>>>(flag, x, h1f, Wk1, Wfold, bfold,
                                       Wk2, bk2, Wk3, bk3, kscale, kclip, invk, kout);
    cudaEventRecord(g_evJoin, g_s1);

    // main: e2 fp32 (exact logits)
    sgemm_kernel<0><<<dim3(D_Q/BN, GY), blk>>>(D_Q, D_H, h1f, D_H, D_H,
        nullptr, 0, We2, be2, logits, D_Q, 0, nullptr, nullptr, nullptr);

    // ---- JOIN: topk ----
    cudaStreamWaitEvent(0, g_evJoin, 0);
    topk_kernel<<<B_ROWS,256>>>(logits, kclip, khot, khotb);

    // ---- decoder ----
    gemm_mma<1,2,1,false,false,2><<<dim3(D_E/128,GY),256,SMEM3>>>(D_Q, D_Q, D_Q, 0,
        khotb, nullptr, nullptr, nullptr, Wcbh, Wcbm, nullptr, invk, nullptr, qh, qm, D_E);
    gemm_mma<2,2,1,true ,false,2><<<dim3(D_H/128,GY),256,SMEM4>>>(D_E, D_E, D_E, 0,
        qh, qm, nullptr, nullptr, Wd1h, Wd1m, bd1, nullptr, nullptr, hdh, hdm, D_H);
    gemm_mma<2,2,1,false,true ,0><<<dim3(D_IN/128,GY),256,SMEM4>>>(D_H, D_H, D_H, 0,
        hdh, hdm, nullptr, nullptr, Wd2h, Wd2m, bd2, nullptr, out, nullptr, nullptr, D_IN);
    if (zptr) tail_kernel<<<1,1>>>(zptr);
}

// round 17
// speedup vs baseline: 1.5138x; 1.5138x over previous
#include <cuda_runtime.h>
#include <cuda_bf16.h>
#include <math.h>
#include <stdint.h>

#define B_ROWS 32768
#define D_IN   256
#define D_H    512
#define D_Q    1024
#define D_E    256
#define K_CAT  (D_IN + D_H)

typedef __nv_bfloat16 bf16;

static cudaStream_t g_s1;
static cudaEvent_t  g_evFork, g_evJoin;
static struct StreamInit {
    StreamInit(){
        cudaStreamCreateWithFlags(&g_s1, cudaStreamNonBlocking);
        cudaEventCreateWithFlags(&g_evFork, cudaEventDisableTiming);
        cudaEventCreateWithFlags(&g_evJoin, cudaEventDisableTiming);
    }
} g_streamInit;

// ---- scratch ----
__device__ float g_h1f[(size_t)B_ROWS*D_H];
__device__ float g_logits[(size_t)B_ROWS*D_Q];
__device__ bf16  g_xh[(size_t)B_ROWS*D_IN], g_xm[(size_t)B_ROWS*D_IN], g_xl[(size_t)B_ROWS*D_IN];
__device__ bf16  g_h1h[(size_t)B_ROWS*D_H], g_h1m[(size_t)B_ROWS*D_H], g_h1l[(size_t)B_ROWS*D_H];
__device__ bf16  g_hk1h[(size_t)B_ROWS*D_H], g_hk1m[(size_t)B_ROWS*D_H], g_hk1l[(size_t)B_ROWS*D_H];
__device__ float g_hk2[(size_t)B_ROWS*D_H];
__device__ bf16  g_khotb[(size_t)B_ROWS*D_Q];
__device__ bf16  g_qh[(size_t)B_ROWS*D_E],  g_qm[(size_t)B_ROWS*D_E];
__device__ bf16  g_hdh[(size_t)B_ROWS*D_H], g_hdm[(size_t)B_ROWS*D_H];
__device__ float g_kclip[B_ROWS], g_invk[B_ROWS];
__device__ float g_We2T[D_H*D_Q];
__device__ float g_Wfold[D_H*D_H];
__device__ float g_bfold[D_H];
__device__ bf16  g_Wch[D_H*K_CAT], g_Wcm[D_H*K_CAT], g_Wcl[D_H*K_CAT];
__device__ bf16  g_Wk2h[D_H*D_H],  g_Wk2m[D_H*D_H],  g_Wk2l[D_H*D_H];
__device__ bf16  g_Wcbh[D_E*D_Q],  g_Wcbm[D_E*D_Q];
__device__ bf16  g_Wd1h[D_H*D_E],  g_Wd1m[D_H*D_E];
__device__ bf16  g_Wd2h[D_IN*D_H], g_Wd2m[D_IN*D_H];

__global__ void split3_kernel(const float* __restrict__ s, bf16* __restrict__ h,
                              bf16* __restrict__ m, bf16* __restrict__ l, int n){
    for (int i = blockIdx.x*blockDim.x + threadIdx.x; i < n; i += gridDim.x*blockDim.x){
        float v = s[i];
        bf16 hb = __float2bfloat16(v);
        float r = v - __bfloat162float(hb);
        bf16 mb = __float2bfloat16(r);
        h[i] = hb; m[i] = mb;
        if (l) l[i] = __float2bfloat16(r - __bfloat162float(mb));
    }
}

__global__ void transpose_kernel(const float* __restrict__ We2, float* __restrict__ We2T){
    int i = blockIdx.x*blockDim.x + threadIdx.x;
    if (i >= D_H*D_Q) return;
    int n = i / D_Q, q = i % D_Q;
    We2T[i] = We2[(size_t)q*D_H + n];
}

__global__ void bfold_kernel(const float* __restrict__ Wk1, const float* __restrict__ bk1,
                             const float* __restrict__ be2, float* __restrict__ bfold){
    const int warp = blockIdx.x*(blockDim.x>>5) + (threadIdx.x>>5);
    const int lane = threadIdx.x & 31;
    if (warp >= D_H) return;
    const float* wr = Wk1 + (size_t)warp*(D_IN + D_Q) + D_IN;
    float s = 0.f;
    for (int q = lane; q < D_Q; q += 32) s += wr[q]*be2[q];
#pragma unroll
    for (int o = 16; o; o >>= 1) s += __shfl_xor_sync(0xffffffffu, s, o);
    if (lane == 0) bfold[warp] = bk1[warp] + s;
}

__global__ void assemble_split_kernel(const float* __restrict__ Wk1, const float* __restrict__ Wfold,
                                      bf16* __restrict__ h, bf16* __restrict__ m, bf16* __restrict__ l){
    for (int i = blockIdx.x*blockDim.x + threadIdx.x; i < D_H*K_CAT; i += gridDim.x*blockDim.x){
        int j = i / K_CAT, c = i % K_CAT;
        float v = (c < D_IN) ? Wk1[(size_t)j*(D_IN+D_Q) + c] : Wfold[(size_t)j*D_H + (c - D_IN)];
        bf16 hb = __float2bfloat16(v);
        float r = v - __bfloat162float(hb);
        bf16 mb = __float2bfloat16(r);
        h[i] = hb; m[i] = mb;
        l[i] = __float2bfloat16(r - __bfloat162float(mb));
    }
}

// ---- packed dual-fp32 FMA ----
static __device__ __forceinline__ uint64_t f32x2_pack(float lo, float hi){
    uint64_t r; asm("mov.b64 %0, {%1,%2};" : "=l"(r) : "f"(lo), "f"(hi)); return r;
}
static __device__ __forceinline__ void f32x2_unpack(uint64_t v, float& lo, float& hi){
    asm("mov.b64 {%0,%1}, %2;" : "=f"(lo), "=f"(hi) : "l"(v));
}
static __device__ __forceinline__ void f32x2_fma(uint64_t& c, uint64_t a, uint64_t b){
    asm("fma.rn.f32x2 %0, %1, %2, %0;" : "+l"(c) : "l"(a), "l"(b));
}

// ============ fp32 SGEMM, FFMA2-rate tiling: 128x128x16 CTA, 128 thr, 16x8/thread ============
// Per-element accumulation order (ascending k) identical to all previous fp32 kernels.
#define BM 128
#define BN 128
#define BK 16

template<int OSPL>
__global__ void __launch_bounds__(128, 2)
sgemm_kernel(int N, int K,
             const float* __restrict__ A0, int lda0, int K0,
             const float* __restrict__ A1, int lda1,
             const float* __restrict__ W,
             const float* __restrict__ bias,
             float* __restrict__ C, int ldc, int do_relu,
             bf16* __restrict__ Ch, bf16* __restrict__ Cm, bf16* __restrict__ Cl)
{
    __shared__ float As[2][BK][BM];
    __shared__ float Bs[2][BK][BN];

    const int tid  = threadIdx.x;           // 0..127
    const int bm   = blockIdx.y * BM;
    const int bn   = blockIdx.x * BN;
    const int tx   = tid & 15, ty = tid >> 4;
    const int tm   = ty * 16;                // 16 rows per thread
    const int tn   = tx * 8;                 // 8 cols per thread
    const int lrow = tid >> 2;               // 0..31
    const int lcol = (tid & 3) << 2;         // 0,4,8,12

    uint64_t acc2[16][4];
#pragma unroll
    for (int i = 0; i < 16; ++i)
#pragma unroll
        for (int jp = 0; jp < 4; ++jp) acc2[i][jp] = 0ull;

    const int nT = K / BK;
    float4 a[4], b[4];

#define FETCH(t) do {                                                              \
    int k0_ = (t) * BK;                                                            \
    const float* Ap_; int la_; int kk_;                                            \
    if (k0_ < K0) { Ap_ = A0; la_ = lda0; kk_ = k0_; }                             \
    else          { Ap_ = A1; la_ = lda1; kk_ = k0_ - K0; }                        \
    a[0] = *(const float4*)(Ap_ + (size_t)(bm + lrow)      * la_ + kk_ + lcol);   \
    a[1] = *(const float4*)(Ap_ + (size_t)(bm + lrow + 32) * la_ + kk_ + lcol);   \
    a[2] = *(const float4*)(Ap_ + (size_t)(bm + lrow + 64) * la_ + kk_ + lcol);   \
    a[3] = *(const float4*)(Ap_ + (size_t)(bm + lrow + 96) * la_ + kk_ + lcol);   \
    b[0] = *(const float4*)(W   + (size_t)(bn + lrow)      * K   + k0_ + lcol);   \
    b[1] = *(const float4*)(W   + (size_t)(bn + lrow + 32) * K   + k0_ + lcol);   \
    b[2] = *(const float4*)(W   + (size_t)(bn + lrow + 64) * K   + k0_ + lcol);   \
    b[3] = *(const float4*)(W   + (size_t)(bn + lrow + 96) * K   + k0_ + lcol);   \
} while (0)

#define STASH(bf) do {                                                   \
    _Pragma("unroll")                                                    \
    for (int g = 0; g < 4; ++g){                                         \
        As[bf][lcol+0][lrow + g*32] = (&a[g].x)[0];                      \
        As[bf][lcol+1][lrow + g*32] = (&a[g].x)[1];                      \
        As[bf][lcol+2][lrow + g*32] = (&a[g].x)[2];                      \
        As[bf][lcol+3][lrow + g*32] = (&a[g].x)[3];                      \
        Bs[bf][lcol+0][lrow + g*32] = (&b[g].x)[0];                      \
        Bs[bf][lcol+1][lrow + g*32] = (&b[g].x)[1];                      \
        Bs[bf][lcol+2][lrow + g*32] = (&b[g].x)[2];                      \
        Bs[bf][lcol+3][lrow + g*32] = (&b[g].x)[3];                      \
    }                                                                    \
} while (0)

    FETCH(0);
    STASH(0);
    __syncthreads();

    int buf = 0;
    for (int t = 0; t < nT; ++t) {
        if (t + 1 < nT) FETCH(t + 1);
#pragma unroll
        for (int kk = 0; kk < BK; ++kk) {
            float av[16], bv[8];
            *(float4*)&av[0]  = *(const float4*)&As[buf][kk][tm];
            *(float4*)&av[4]  = *(const float4*)&As[buf][kk][tm + 4];
            *(float4*)&av[8]  = *(const float4*)&As[buf][kk][tm + 8];
            *(float4*)&av[12] = *(const float4*)&As[buf][kk][tm + 12];
            *(float4*)&bv[0]  = *(const float4*)&Bs[buf][kk][tn];
            *(float4*)&bv[4]  = *(const float4*)&Bs[buf][kk][tn + 4];
            uint64_t bp[4];
            bp[0] = f32x2_pack(bv[0], bv[1]);
            bp[1] = f32x2_pack(bv[2], bv[3]);
            bp[2] = f32x2_pack(bv[4], bv[5]);
            bp[3] = f32x2_pack(bv[6], bv[7]);
#pragma unroll
            for (int i = 0; i < 16; ++i) {
                uint64_t ad = f32x2_pack(av[i], av[i]);
#pragma unroll
                for (int jp = 0; jp < 4; ++jp)
                    f32x2_fma(acc2[i][jp], ad, bp[jp]);
            }
        }
        if (t + 1 < nT) STASH(buf ^ 1);
        __syncthreads();
        buf ^= 1;
    }

    float bj[8];
#pragma unroll
    for (int j = 0; j < 8; ++j) bj[j] = bias ? bias[bn + tn + j] : 0.f;

#pragma unroll
    for (int i = 0; i < 16; ++i) {
        const int row = bm + tm + i;
        float v[8];
#pragma unroll
        for (int jp = 0; jp < 4; ++jp)
            f32x2_unpack(acc2[i][jp], v[2*jp], v[2*jp+1]);
#pragma unroll
        for (int j = 0; j < 8; ++j) {
            float t = v[j] + bj[j];
            if (do_relu) t = fmaxf(t, 0.f);
            v[j] = t;
        }
        float* cp = C + (size_t)row * ldc + bn + tn;
        *(float4*)cp       = make_float4(v[0], v[1], v[2], v[3]);
        *(float4*)(cp + 4) = make_float4(v[4], v[5], v[6], v[7]);
        if (OSPL == 3){
            uint32_t ph[4], pm[4], pl[4];
#pragma unroll
            for (int jp = 0; jp < 4; ++jp){
                float v0 = v[2*jp], v1 = v[2*jp+1];
                bf16 h0 = __float2bfloat16(v0), h1 = __float2bfloat16(v1);
                float r0 = v0 - __bfloat162float(h0), r1 = v1 - __bfloat162float(h1);
                bf16 m0 = __float2bfloat16(r0), m1 = __float2bfloat16(r1);
                bf16 l0 = __float2bfloat16(r0 - __bfloat162float(m0));
                bf16 l1 = __float2bfloat16(r1 - __bfloat162float(m1));
                ph[jp] = ((uint32_t)__bfloat16_as_ushort(h1) << 16) | __bfloat16_as_ushort(h0);
                pm[jp] = ((uint32_t)__bfloat16_as_ushort(m1) << 16) | __bfloat16_as_ushort(m0);
                pl[jp] = ((uint32_t)__bfloat16_as_ushort(l1) << 16) | __bfloat16_as_ushort(l0);
            }
            *(uint4*)(Ch + (size_t)row*ldc + bn + tn) = make_uint4(ph[0], ph[1], ph[2], ph[3]);
            *(uint4*)(Cm + (size_t)row*ldc + bn + tn) = make_uint4(pm[0], pm[1], pm[2], pm[3]);
            *(uint4*)(Cl + (size_t)row*ldc + bn + tn) = make_uint4(pl[0], pl[1], pl[2], pl[3]);
        }
    }
#undef FETCH
#undef STASH
}

// =============== HMMA multi-term split-bf16 GEMM (verified R5-R13) ===============
#define LDSM 40
#define TILE_E (128*LDSM)

static __device__ __forceinline__ void cpa16(bf16* dst, const bf16* src){
    uint32_t d = (uint32_t)__cvta_generic_to_shared(dst);
    asm volatile("cp.async.cg.shared.global [%0], [%1], 16;" :: "r"(d), "l"(src));
}
static __device__ __forceinline__ void mma16816(float* c, const uint32_t* a, const uint32_t* b){
    asm volatile("mma.sync.aligned.m16n8k16.row.col.f32.bf16.bf16.f32 "
        "{%0,%1,%2,%3},{%4,%5,%6,%7},{%8,%9},{%0,%1,%2,%3};"
        : "+f"(c[0]), "+f"(c[1]), "+f"(c[2]), "+f"(c[3])
        : "r"(a[0]), "r"(a[1]), "r"(a[2]), "r"(a[3]), "r"(b[0]), "r"(b[1]));
}

template<int NA, int NB, int MS, bool RELU, bool OF32, int OSPL>
__global__ void __launch_bounds__(256,1)
gemm_mma(int K, int K0, int lda0, int lda1,
         const bf16* __restrict__ A0h, const bf16* __restrict__ A0m, const bf16* __restrict__ A0l,
         const bf16* __restrict__ A1h, const bf16* __restrict__ A1m, const bf16* __restrict__ A1l,
         const bf16* __restrict__ B0,  const bf16* __restrict__ B1,  const bf16* __restrict__ B2,
         const float* __restrict__ bias, const float* __restrict__ rowScale,
         float* __restrict__ C32, bf16* __restrict__ Ch, bf16* __restrict__ Cm,
         bf16* __restrict__ Cl, int ldc)
{
    extern __shared__ bf16 sm[];
    constexpr int NARR = NA + NB;
    const int tid = threadIdx.x, lane = tid & 31, wid = tid >> 5;
    const int bm = blockIdx.y*128, bn = blockIdx.x*128;
    const int wm = (wid >> 2)*64, wn = (wid & 3)*32;

    float acc[4][4][4];
#pragma unroll
    for (int mi = 0; mi < 4; ++mi)
#pragma unroll
        for (int ni = 0; ni < 4; ++ni)
#pragma unroll
            for (int e = 0; e < 4; ++e) acc[mi][ni][e] = 0.f;

    const int nT = K / 32;

    auto loadStage = [&](int t, int stage){
        bf16* base = sm + (size_t)stage*NARR*TILE_E;
        const int kc = t*32;
        const bf16* Aarr[3]; int ld, co;
        if (kc < K0){ Aarr[0]=A0h; Aarr[1]=A0m; Aarr[2]=A0l; ld=lda0; co=kc; }
        else        { Aarr[0]=A1h; Aarr[1]=A1m; Aarr[2]=A1l; ld=lda1; co=kc-K0; }
        const bf16* Barr[3] = {B0, B1, B2};
#pragma unroll
        for (int arr = 0; arr < NA; ++arr)
#pragma unroll
            for (int s = tid; s < 512; s += 256){
                int r = s >> 2, c = s & 3;
                cpa16(base + arr*TILE_E + r*LDSM + c*8, Aarr[arr] + (size_t)(bm + r)*ld + co + c*8);
            }
#pragma unroll
        for (int arr = 0; arr < NB; ++arr)
#pragma unroll
            for (int s = tid; s < 512; s += 256){
                int r = s >> 2, c = s & 3;
                cpa16(base + (NA+arr)*TILE_E + r*LDSM + c*8, Barr[arr] + (size_t)(bn + r)*K + kc + c*8);
            }
        asm volatile("cp.async.commit_group;" ::: "memory");
    };

    loadStage(0, 0);

    for (int t = 0; t < nT; ++t){
        const int stage = t & 1;
        if (t + 1 < nT){
            loadStage(t + 1, stage ^ 1);
            asm volatile("cp.async.wait_group 1;" ::: "memory");
        } else {
            asm volatile("cp.async.wait_group 0;" ::: "memory");
        }
        __syncthreads();

        const bf16* base = sm + (size_t)stage*NARR*TILE_E;
#pragma unroll
        for (int ks = 0; ks < 2; ++ks){
            const int k0 = ks*16 + (lane & 3)*2;
            const int ar = wm + (lane >> 2);
            uint32_t afr[NA][4][4], bfr[NB][4][2];
#pragma unroll
            for (int arr = 0; arr < NA; ++arr){
                const bf16* sA = base + arr*TILE_E;
#pragma unroll
                for (int mi = 0; mi < 4; ++mi){
                    const bf16* p = sA + (size_t)(ar + mi*16)*LDSM + k0;
                    afr[arr][mi][0] = *(const uint32_t*)(p);
                    afr[arr][mi][1] = *(const uint32_t*)(p + 8*LDSM);
                    afr[arr][mi][2] = *(const uint32_t*)(p + 8);
                    afr[arr][mi][3] = *(const uint32_t*)(p + 8*LDSM + 8);
                }
            }
#pragma unroll
            for (int arr = 0; arr < NB; ++arr){
                const bf16* sB = base + (NA+arr)*TILE_E;
#pragma unroll
                for (int ni = 0; ni < 4; ++ni){
                    const bf16* p = sB + (size_t)(wn + ni*8 + (lane >> 2))*LDSM + k0;
                    bfr[arr][ni][0] = *(const uint32_t*)(p);
                    bfr[arr][ni][1] = *(const uint32_t*)(p + 8);
                }
            }
#pragma unroll
            for (int a = 0; a < NA; ++a)
#pragma unroll
                for (int b = 0; b < NB; ++b){
                    if (a + b <= MS){
#pragma unroll
                        for (int mi = 0; mi < 4; ++mi)
#pragma unroll
                            for (int ni = 0; ni < 4; ++ni)
                                mma16816(acc[mi][ni], afr[a][mi], bfr[b][ni]);
                    }
                }
        }
        __syncthreads();
    }

#pragma unroll
    for (int mi = 0; mi < 4; ++mi){
        const int r0 = bm + wm + mi*16 + (lane >> 2);
        const int r1 = r0 + 8;
        const float rs0 = rowScale ? rowScale[r0] : 1.f;
        const float rs1 = rowScale ? rowScale[r1] : 1.f;
#pragma unroll
        for (int ni = 0; ni < 4; ++ni){
            const int c0 = bn + wn + ni*8 + (lane & 3)*2;
            const float b0 = bias ? bias[c0] : 0.f;
            const float b1 = bias ? bias[c0 + 1] : 0.f;
            float v00 = acc[mi][ni][0] + b0, v01 = acc[mi][ni][1] + b1;
            float v10 = acc[mi][ni][2] + b0, v11 = acc[mi][ni][3] + b1;
            if (RELU){ v00 = fmaxf(v00, 0.f); v01 = fmaxf(v01, 0.f);
                       v10 = fmaxf(v10, 0.f); v11 = fmaxf(v11, 0.f); }
            v00 *= rs0; v01 *= rs0; v10 *= rs1; v11 *= rs1;
            if (OF32){
                *(float2*)(C32 + (size_t)r0*ldc + c0) = make_float2(v00, v01);
                *(float2*)(C32 + (size_t)r1*ldc + c0) = make_float2(v10, v11);
            }
            if (OSPL >= 2){
                bf16 h00 = __float2bfloat16(v00), h01 = __float2bfloat16(v01);
                bf16 h10 = __float2bfloat16(v10), h11 = __float2bfloat16(v11);
                float r00 = v00 - __bfloat162float(h00), r01 = v01 - __bfloat162float(h01);
                float r10 = v10 - __bfloat162float(h10), r11 = v11 - __bfloat162float(h11);
                bf16 m00 = __float2bfloat16(r00), m01 = __float2bfloat16(r01);
                bf16 m10 = __float2bfloat16(r10), m11 = __float2bfloat16(r11);
                *(uint32_t*)(Ch + (size_t)r0*ldc + c0) =
                    ((uint32_t)__bfloat16_as_ushort(h01) << 16) | __bfloat16_as_ushort(h00);
                *(uint32_t*)(Ch + (size_t)r1*ldc + c0) =
                    ((uint32_t)__bfloat16_as_ushort(h11) << 16) | __bfloat16_as_ushort(h10);
                *(uint32_t*)(Cm + (size_t)r0*ldc + c0) =
                    ((uint32_t)__bfloat16_as_ushort(m01) << 16) | __bfloat16_as_ushort(m00);
                *(uint32_t*)(Cm + (size_t)r1*ldc + c0) =
                    ((uint32_t)__bfloat16_as_ushort(m11) << 16) | __bfloat16_as_ushort(m10);
                if (OSPL == 3){
                    bf16 l00 = __float2bfloat16(r00 - __bfloat162float(m00));
                    bf16 l01 = __float2bfloat16(r01 - __bfloat162float(m01));
                    bf16 l10 = __float2bfloat16(r10 - __bfloat162float(m10));
                    bf16 l11 = __float2bfloat16(r11 - __bfloat162float(m11));
                    *(uint32_t*)(Cl + (size_t)r0*ldc + c0) =
                        ((uint32_t)__bfloat16_as_ushort(l01) << 16) | __bfloat16_as_ushort(l00);
                    *(uint32_t*)(Cl + (size_t)r1*ldc + c0) =
                        ((uint32_t)__bfloat16_as_ushort(l11) << 16) | __bfloat16_as_ushort(l10);
                }
            }
        }
    }
}

__global__ void kpred_kernel(const float* __restrict__ hk2, const float* __restrict__ wk3,
                             const float* __restrict__ bk3, const float* __restrict__ kscale,
                             float* __restrict__ kclip, float* __restrict__ invk, float* __restrict__ kout)
{
    __shared__ float ws[D_H];
    for (int j = threadIdx.x; j < D_H; j += blockDim.x) ws[j] = wk3[j];
    __syncthreads();
    const int warp = blockIdx.x*(blockDim.x>>5) + (threadIdx.x>>5);
    const int lane = threadIdx.x & 31;
    if (warp >= B_ROWS) return;
    const float* h = hk2 + (size_t)warp*D_H;
    float s = 0.f;
    for (int j = lane; j < D_H; j += 32) s += h[j]*ws[j];
#pragma unroll
    for (int o = 16; o; o >>= 1) s += __shfl_xor_sync(0xffffffffu, s, o);
    if (lane == 0){
        float z = s + bk3[0];
        float k = (1.f/(1.f + expf(-z))) * 1024.f;
        float ks = 1.f/(1.f + expf(-kscale[0]));
        k = fminf(fmaxf(k*ks*2.f, 1.f), 1024.f);
        kclip[warp] = k; invk[warp] = 1.f/k;
        if (kout) kout[warp] = k;
    }
}

__global__ void topk_kernel(const float* __restrict__ logits, const float* __restrict__ kclip,
                            float* __restrict__ khot, bf16* __restrict__ khotb)
{
    __shared__ unsigned keys[D_Q];
    __shared__ int hist[256], scanbuf[256], warpsum[8], sBin;
    const int row = blockIdx.x, tid = threadIdx.x;
    float4 v = ((const float4*)(logits + (size_t)row*D_Q))[tid];
    { unsigned u;
      u=__float_as_uint(v.x); keys[tid*4+0]=(int)u>=0?(u|0x80000000u):~u;
      u=__float_as_uint(v.y); keys[tid*4+1]=(int)u>=0?(u|0x80000000u):~u;
      u=__float_as_uint(v.z); keys[tid*4+2]=(int)u>=0?(u|0x80000000u):~u;
      u=__float_as_uint(v.w); keys[tid*4+3]=(int)u>=0?(u|0x80000000u):~u; }
    int c = (int)ceilf(kclip[row]); c = max(1, min(D_Q, c));
    __syncthreads();
    unsigned prefix = 0; int want = c;
#pragma unroll
    for (int byte = 3; byte >= 0; --byte){
        hist[tid] = 0; __syncthreads();
        const unsigned mask = (byte==3) ? 0u : (0xFFFFFFFFu << ((byte+1)*8));
#pragma unroll
        for (int e = 0; e < 4; ++e){
            unsigned kk = keys[tid*4+e];
            if ((kk & mask) == prefix) atomicAdd(&hist[(kk >> (byte*8)) & 0xFF], 1);
        }
        __syncthreads();
        scanbuf[tid] = hist[tid]; __syncthreads();
        for (int d = 1; d < 256; d <<= 1){
            int add = (tid+d < 256) ? scanbuf[tid+d] : 0; __syncthreads();
            scanbuf[tid] += add; __syncthreads();
        }
        int nb = (tid < 255) ? scanbuf[tid+1] : 0;
        if (scanbuf[tid] >= want && nb < want) sBin = tid;
        __syncthreads();
        int bin = sBin;
        want -= (bin < 255) ? scanbuf[bin+1] : 0;
        prefix |= ((unsigned)bin) << (byte*8);
        __syncthreads();
    }
    const unsigned thr = prefix; const int rem = want;
    int gtf[4], eqf[4], pre[4], lc = 0;
#pragma unroll
    for (int e = 0; e < 4; ++e){
        unsigned kk = keys[tid*4+e];
        gtf[e] = (kk > thr); eqf[e] = (kk == thr); pre[e] = lc; lc += eqf[e];
    }
    const int lane = tid & 31, wid = tid >> 5;
    int inc = lc;
#pragma unroll
    for (int o = 1; o < 32; o <<= 1){ int y = __shfl_up_sync(0xffffffffu, inc, o); if (lane >= o) inc += y; }
    if (lane == 31) warpsum[wid] = inc;
    __syncthreads();
    if (tid == 0){ int run = 0; for (int i = 0; i < 8; ++i){ int t = warpsum[i]; warpsum[i] = run; run += t; } }
    __syncthreads();
    const int base = warpsum[wid] + inc - lc;
    float4 o;
    o.x = (gtf[0] || (eqf[0] && (base+pre[0]) < rem)) ? 1.f : 0.f;
    o.y = (gtf[1] || (eqf[1] && (base+pre[1]) < rem)) ? 1.f : 0.f;
    o.z = (gtf[2] || (eqf[2] && (base+pre[2]) < rem)) ? 1.f : 0.f;
    o.w = (gtf[3] || (eqf[3] && (base+pre[3]) < rem)) ? 1.f : 0.f;
    ((float4*)(khot + (size_t)row*D_Q))[tid] = o;
    uint32_t p0 = ((uint32_t)__bfloat16_as_ushort(__float2bfloat16(o.y)) << 16) | __bfloat16_as_ushort(__float2bfloat16(o.x));
    uint32_t p1 = ((uint32_t)__bfloat16_as_ushort(__float2bfloat16(o.w)) << 16) | __bfloat16_as_ushort(__float2bfloat16(o.z));
    ((uint2*)(khotb + (size_t)row*D_Q))[tid] = make_uint2(p0, p1);
}

__global__ void tail_kernel(float* zptr){ *zptr = 0.f; }

extern "C" void kernel_launch(void* const* d_in, const int* in_sizes, int n_in,
                              void* d_out, int out_size)
{
    const float* x      = (const float*)d_in[0];
    const float* We1    = (const float*)d_in[1];
    const float* be1    = (const float*)d_in[2];
    const float* We2    = (const float*)d_in[3];
    const float* be2    = (const float*)d_in[4];
    const float* Wcb    = (const float*)d_in[5];
    const float* Wd1    = (const float*)d_in[6];
    const float* bd1    = (const float*)d_in[7];
    const float* Wd2    = (const float*)d_in[8];
    const float* bd2    = (const float*)d_in[9];
    const float* Wk1    = (const float*)d_in[10];
    const float* bk1    = (const float*)d_in[11];
    const float* Wk2    = (const float*)d_in[12];
    const float* bk2    = (const float*)d_in[13];
    const float* Wk3    = (const float*)d_in[14];
    const float* bk3    = (const float*)d_in[15];
    const float* kscale = (const float*)d_in[16];

    bf16 *xh,*xm,*xl,*h1h,*h1m,*h1l,*hk1h,*hk1m,*hk1l,*khotb,*qh,*qm,*hdh,*hdm;
    bf16 *Wch,*Wcm,*Wcl,*Wk2h,*Wk2m,*Wk2l,*Wcbh,*Wcbm,*Wd1h,*Wd1m,*Wd2h,*Wd2m;
    float *h1f,*logits,*hk2,*kclip,*invk,*We2T,*Wfold,*bfold;
    cudaGetSymbolAddress((void**)&h1f,g_h1f);
    cudaGetSymbolAddress((void**)&logits,g_logits);
    cudaGetSymbolAddress((void**)&xh,g_xh);     cudaGetSymbolAddress((void**)&xm,g_xm);
    cudaGetSymbolAddress((void**)&xl,g_xl);
    cudaGetSymbolAddress((void**)&h1h,g_h1h);   cudaGetSymbolAddress((void**)&h1m,g_h1m);
    cudaGetSymbolAddress((void**)&h1l,g_h1l);
    cudaGetSymbolAddress((void**)&hk1h,g_hk1h); cudaGetSymbolAddress((void**)&hk1m,g_hk1m);
    cudaGetSymbolAddress((void**)&hk1l,g_hk1l);
    cudaGetSymbolAddress((void**)&hk2,g_hk2);
    cudaGetSymbolAddress((void**)&khotb,g_khotb);
    cudaGetSymbolAddress((void**)&qh,g_qh);     cudaGetSymbolAddress((void**)&qm,g_qm);
    cudaGetSymbolAddress((void**)&hdh,g_hdh);   cudaGetSymbolAddress((void**)&hdm,g_hdm);
    cudaGetSymbolAddress((void**)&We2T,g_We2T); cudaGetSymbolAddress((void**)&Wfold,g_Wfold);
    cudaGetSymbolAddress((void**)&bfold,g_bfold);
    cudaGetSymbolAddress((void**)&Wch,g_Wch);   cudaGetSymbolAddress((void**)&Wcm,g_Wcm);
    cudaGetSymbolAddress((void**)&Wcl,g_Wcl);
    cudaGetSymbolAddress((void**)&Wk2h,g_Wk2h); cudaGetSymbolAddress((void**)&Wk2m,g_Wk2m);
    cudaGetSymbolAddress((void**)&Wk2l,g_Wk2l);
    cudaGetSymbolAddress((void**)&Wcbh,g_Wcbh); cudaGetSymbolAddress((void**)&Wcbm,g_Wcbm);
    cudaGetSymbolAddress((void**)&Wd1h,g_Wd1h); cudaGetSymbolAddress((void**)&Wd1m,g_Wd1m);
    cudaGetSymbolAddress((void**)&Wd2h,g_Wd2h); cudaGetSymbolAddress((void**)&Wd2m,g_Wd2m);
    cudaGetSymbolAddress((void**)&kclip,g_kclip); cudaGetSymbolAddress((void**)&invk,g_invk);

    float* out = (float*)d_out;
    const long long reconN = (long long)B_ROWS*D_IN, khotN = (long long)B_ROWS*D_Q;
    const long long osz = (long long)out_size;
    float* khot = logits;
    if (osz >= reconN + khotN) khot = out + reconN;
    float *kout = nullptr, *zptr = nullptr;
    const long long tail = osz - (reconN + khotN);
    if (tail == 1 + (long long)B_ROWS){ zptr = out + reconN + khotN; kout = zptr + 1; }
    else if (tail == (long long)B_ROWS){ kout = out + reconN + khotN; }

    const int SMEM6 = 2*6*TILE_E*(int)sizeof(bf16);
    const int SMEM4 = 2*4*TILE_E*(int)sizeof(bf16);
    const int SMEM3 = 2*3*TILE_E*(int)sizeof(bf16);
    cudaFuncSetAttribute(gemm_mma<3,3,2,true ,false,3>, cudaFuncAttributeMaxDynamicSharedMemorySize, SMEM6);
    cudaFuncSetAttribute(gemm_mma<3,3,2,true ,true ,0>, cudaFuncAttributeMaxDynamicSharedMemorySize, SMEM6);
    cudaFuncSetAttribute(gemm_mma<1,2,1,false,false,2>, cudaFuncAttributeMaxDynamicSharedMemorySize, SMEM3);
    cudaFuncSetAttribute(gemm_mma<2,2,1,true ,false,2>, cudaFuncAttributeMaxDynamicSharedMemorySize, SMEM4);
    cudaFuncSetAttribute(gemm_mma<2,2,1,false,true ,0>, cudaFuncAttributeMaxDynamicSharedMemorySize, SMEM4);

    // ---- fold precompute ----
    transpose_kernel<<<(D_H*D_Q + 255)/256, 256>>>(We2, We2T);
    sgemm_kernel<0><<<dim3(D_H/BN, D_H/BM), 128>>>(D_H, D_Q, Wk1 + D_IN, D_IN + D_Q, D_Q,
        nullptr, 0, We2T, nullptr, Wfold, D_H, 0, nullptr, nullptr, nullptr);
    bfold_kernel<<<(D_H*32 + 255)/256, 256>>>(Wk1, bk1, be2, bfold);
    assemble_split_kernel<<<256, 256>>>(Wk1, Wfold, Wch, Wcm, Wcl);

    // ---- splits ----
    split3_kernel<<<1024,256>>>(x,   xh,   xm,   xl,     B_ROWS*D_IN);
    split3_kernel<<<128 ,256>>>(Wk2, Wk2h, Wk2m, Wk2l,   D_H*D_H);
    split3_kernel<<<128 ,256>>>(Wcb, Wcbh, Wcbm, nullptr, D_E*D_Q);
    split3_kernel<<<128 ,256>>>(Wd1, Wd1h, Wd1m, nullptr, D_H*D_E);
    split3_kernel<<<128 ,256>>>(Wd2, Wd2h, Wd2m, nullptr, D_IN*D_H);

    const int GY = B_ROWS/128;

    // ---- e1 (fp32 exact; emits h1 fp32 + fused 3-way split) ----
    sgemm_kernel<3><<<dim3(D_H/BN, GY), 128>>>(D_H, D_IN, x, D_IN, D_IN,
        nullptr, 0, We1, be1, h1f, D_H, 1, h1h, h1m, h1l);

    // ---- FORK: 6-term k-path (tensor pipe) || e2 fp32 ----
    cudaEventRecord(g_evFork, 0);
    cudaStreamWaitEvent(g_s1, g_evFork, 0);

    gemm_mma<3,3,2,true ,false,3><<<dim3(D_H/128,GY),256,SMEM6,g_s1>>>(K_CAT, D_IN, D_IN, D_H,
        xh, xm, xl, h1h, h1m, h1l, Wch, Wcm, Wcl,
        bfold, nullptr, nullptr, hk1h, hk1m, hk1l, D_H);
    gemm_mma<3,3,2,true ,true ,0><<<dim3(D_H/128,GY),256,SMEM6,g_s1>>>(D_H, D_H, D_H, 0,
        hk1h, hk1m, hk1l, nullptr, nullptr, nullptr, Wk2h, Wk2m, Wk2l,
        bk2, nullptr, hk2, nullptr, nullptr, nullptr, D_H);
    kpred_kernel<<<B_ROWS/8,256,0,g_s1>>>(hk2, Wk3, bk3, kscale, kclip, invk, kout);
    cudaEventRecord(g_evJoin, g_s1);

    // main: e2 fp32 (exact logits; FFMA2-rate tiling)
    sgemm_kernel<0><<<dim3(D_Q/BN, GY), 128>>>(D_Q, D_H, h1f, D_H, D_H,
        nullptr, 0, We2, be2, logits, D_Q, 0, nullptr, nullptr, nullptr);

    // ---- JOIN: topk ----
    cudaStreamWaitEvent(0, g_evJoin, 0);
    topk_kernel<<<B_ROWS,256>>>(logits, kclip, khot, khotb);

    // ---- decoder ----
    gemm_mma<1,2,1,false,false,2><<<dim3(D_E/128,GY),256,SMEM3>>>(D_Q, D_Q, D_Q, 0,
        khotb, nullptr, nullptr, nullptr, nullptr, nullptr, Wcbh, Wcbm, nullptr,
        nullptr, invk, nullptr, qh, qm, nullptr, D_E);
    gemm_mma<2,2,1,true ,false,2><<<dim3(D_H/128,GY),256,SMEM4>>>(D_E, D_E, D_E, 0,
        qh, qm, nullptr, nullptr, nullptr, nullptr, Wd1h, Wd1m, nullptr,
        bd1, nullptr, nullptr, hdh, hdm, nullptr, D_H);
    gemm_mma<2,2,1,false,true ,0><<<dim3(D_IN/128,GY),256,SMEM4>>>(D_H, D_H, D_H, 0,
        hdh, hdm, nullptr, nullptr, nullptr, nullptr, Wd2h, Wd2m, nullptr,
        bd2, nullptr, out, nullptr, nullptr, nullptr, D_IN);
    if (zptr) tail_kernel<<<1,1>>>(zptr);
}